// round 16
// baseline (speedup 1.0000x reference)
#include <cuda_runtime.h>
#include <cuda_bf16.h>
#include <cstdint>
#include <cstddef>

#define L_DIM 512
#define S_DIM 128
#define IN_DIM 256
#define OUT_F 128
using u32 = unsigned int;
using uch = unsigned char;
using us  = unsigned short;

__device__ __forceinline__ u32 smem_u32(const void* p){
    u32 a; asm("{ .reg .u64 t; cvta.to.shared.u64 t,%1; cvt.u32.u64 %0,t;}":"=r"(a):"l"(p)); return a;
}
__device__ __forceinline__ void cp16(u32 d, const void* s){
    asm volatile("cp.async.cg.shared.global [%0],[%1],16;"::"r"(d),"l"(s));
}
#define CPC()  asm volatile("cp.async.commit_group;":::"memory")
#define CPW0() asm volatile("cp.async.wait_group 0;":::"memory")
#define CPW1() asm volatile("cp.async.wait_group 1;":::"memory")
#define CPW2() asm volatile("cp.async.wait_group 2;":::"memory")
#define LDSM4(R,a) asm volatile("ldmatrix.sync.aligned.m8n8.x4.shared.b16 {%0,%1,%2,%3},[%4];" \
    :"=r"((R)[0]),"=r"((R)[1]),"=r"((R)[2]),"=r"((R)[3]):"r"(a))
#define MMA(C,A,b0,b1) asm volatile( \
    "mma.sync.aligned.m16n8k16.row.col.f32.bf16.bf16.f32 {%0,%1,%2,%3},{%4,%5,%6,%7},{%8,%9},{%0,%1,%2,%3};" \
    :"+f"((C)[0]),"+f"((C)[1]),"+f"((C)[2]),"+f"((C)[3]) \
    :"r"((A)[0]),"r"((A)[1]),"r"((A)[2]),"r"((A)[3]),"r"(b0),"r"(b1))

__device__ __forceinline__ void bsplit(float v, us& h, us& l){
    __nv_bfloat16 hb = __float2bfloat16(v);
    __nv_bfloat16 lb = __float2bfloat16(v - __bfloat162float(hb));
    h = __bfloat16_as_ushort(hb); l = __bfloat16_as_ushort(lb);
}
__device__ __forceinline__ void packHL(float a, float b, u32& H, u32& L){
    us h0,l0,h1,l1; bsplit(a,h0,l0); bsplit(b,h1,l1);
    H = (u32)h0 | ((u32)h1<<16); L = (u32)l0 | ((u32)l1<<16);
}

// Operand images, plain row-major bf16, k-contiguous rows (256B rows for R/L).
__device__ uch g_Rh[16384*256];  // row = j*32+e, 128 s
__device__ uch g_Rl[16384*256];
__device__ uch g_Lh[16384*256];  // row = i*32+d, 128 s
__device__ uch g_Ll[16384*256];
__device__ uch g_Wh[128*2048];   // row = f, k = e*32+d
__device__ uch g_Wl[128*2048];
__device__ uch g_Gh[536870912];  // row = i*512+j, k = e*32+d (2048B rows)
__device__ uch g_Gl[536870912];

// ================= kA: LN + proj + mask -> bf16 hi/lo images =================
#define KA_WPITCH 66
#define KA_SMEM_FLOATS (IN_DIM*KA_WPITCH + 32*IN_DIM + 64)
__global__ void __launch_bounds__(256) kA(
    const float* __restrict__ x, const float* __restrict__ mask,
    const float* __restrict__ W, const float* __restrict__ b)
{
    extern __shared__ float sma[];
    float* W_sm = sma;
    float* x_sm = sma + IN_DIM*KA_WPITCH;
    float* sW_sm = x_sm + 32*IN_DIM;
    const int t = threadIdx.x;
    {
        const float4* Wg = (const float4*)W;
        #pragma unroll
        for (int q = 0; q < 16; q++){
            int i4 = t + 256*q; float4 v = Wg[i4];
            int lin = i4*4, k = lin>>8, c = lin&255;
            W_sm[(c+0)*KA_WPITCH+k]=v.x; W_sm[(c+1)*KA_WPITCH+k]=v.y;
            W_sm[(c+2)*KA_WPITCH+k]=v.z; W_sm[(c+3)*KA_WPITCH+k]=v.w;
        }
    }
    const int row0 = blockIdx.x*32;
    {
        const float4* xs = (const float4*)(x + (size_t)row0*IN_DIM);
        float4* xd = (float4*)x_sm;
        #pragma unroll
        for (int q = 0; q < 8; q++) xd[t+256*q] = xs[t+256*q];
    }
    __syncthreads();
    if (t < 64){
        float s = 0.f;
        #pragma unroll 8
        for (int c = 0; c < IN_DIM; c++) s += W_sm[c*KA_WPITCH+t];
        sW_sm[t] = s;
    }
    __syncthreads();
    const int w = t>>5, lane = t&31;
    #pragma unroll 1
    for (int rr = 0; rr < 4; rr++){
        const int rl = w*4+rr;
        float s1 = 0.f, s2 = 0.f;
        #pragma unroll
        for (int q = 0; q < 8; q++){ float v = x_sm[rl*IN_DIM+lane+32*q]; s1 += v; s2 += v*v; }
        #pragma unroll
        for (int off = 16; off; off >>= 1){
            s1 += __shfl_xor_sync(0xffffffffu, s1, off);
            s2 += __shfl_xor_sync(0xffffffffu, s2, off);
        }
        const float mu = s1*(1.f/256.f);
        const float rs = rsqrtf(s2*(1.f/256.f) - mu*mu + 1e-5f);
        float a0 = 0.f, a1 = 0.f;
        {
            const float* xr = x_sm + rl*IN_DIM;
            const float* wp = W_sm + 2*lane;
            #pragma unroll 8
            for (int c = 0; c < IN_DIM; c += 4){
                float4 xv = *(const float4*)&xr[c];
                float2 p0 = *(const float2*)&wp[(c+0)*KA_WPITCH];
                float2 p1 = *(const float2*)&wp[(c+1)*KA_WPITCH];
                float2 p2 = *(const float2*)&wp[(c+2)*KA_WPITCH];
                float2 p3 = *(const float2*)&wp[(c+3)*KA_WPITCH];
                a0 += xv.x*p0.x; a1 += xv.x*p0.y; a0 += xv.y*p1.x; a1 += xv.y*p1.y;
                a0 += xv.z*p2.x; a1 += xv.z*p2.y; a0 += xv.w*p3.x; a1 += xv.w*p3.y;
            }
        }
        const int row = row0+rl;
        const float m = mask[row];
        const int k0 = 2*lane;
        float v0 = (rs*(a0 - mu*sW_sm[k0  ]) + b[k0  ])*m;
        float v1 = (rs*(a1 - mu*sW_sm[k0+1]) + b[k0+1])*m;
        const int s = row>>9, ip = row&511;
        us h0,l0,h1,l1; bsplit(v0,h0,l0); bsplit(v1,h1,l1);
        if (lane < 16){
            size_t b0 = ((size_t)ip*32 + k0)*256 + s*2;
            *(us*)(g_Lh+b0)=h0; *(us*)(g_Ll+b0)=l0;
            *(us*)(g_Lh+b0+256)=h1; *(us*)(g_Ll+b0+256)=l1;
        } else {
            size_t b0 = ((size_t)ip*32 + (k0-32))*256 + s*2;
            *(us*)(g_Rh+b0)=h0; *(us*)(g_Rl+b0)=l0;
            *(us*)(g_Rh+b0+256)=h1; *(us*)(g_Rl+b0+256)=l1;
        }
    }
}

// ================= kW: out_weights [d*32+e][f] -> Wt[f][e*32+d] ===============
__global__ void __launch_bounds__(256) kW(const float* __restrict__ Wout){
    const int f = blockIdx.x, t = threadIdx.x;
    #pragma unroll
    for (int q = 0; q < 4; q++){
        int k = t + 256*q;
        int d = k&31, e = k>>5;
        us h,l; bsplit(Wout[(size_t)(d*32+e)*OUT_F + f], h, l);
        *(us*)(g_Wh + (size_t)f*2048 + k*2) = h;
        *(us*)(g_Wl + (size_t)f*2048 + k*2) = l;
    }
}

// ================= kB1: G as square GEMM M=(j,e) N=(i,d) K=128s ===============
// CTA tile 128x128, K in 4 chunks of 32, kB2-style warp layout (4 j-e warps x
// 2 i-d warps). Chunk buffer 32KB: Ah 8K | Al 8K | Bh 8K | Bl 8K; dbuf 64KB.
// After compute, buffers recycled for bf16 hi/lo staging of 16 complete G rows.
#define KB1_SMEM 65536
__global__ void __launch_bounds__(256,2) kB1(){
    extern __shared__ __align__(128) uch sm1[];
    const u32 sb = smem_u32(sm1);
    const int t = threadIdx.x, w = t>>5, lane = t&31;
    const int j0 = blockIdx.x*4, i0 = blockIdx.y*4;

    auto issue = [&](int c, int buf){
        size_t abase = (size_t)blockIdx.x*128*256 + c*64;
        size_t bbase = (size_t)blockIdx.y*128*256 + c*64;
        #pragma unroll
        for (int q = 0; q < 2; q++){
            int v = t+256*q, row = v>>2, ch = v&3;
            u32 sw = (u32)(((u32)ch ^ ((row>>1)&3))<<4);
            u32 d = sb + buf*32768 + row*64 + sw;
            size_t ao = abase + (size_t)row*256 + ch*16;
            size_t bo = bbase + (size_t)row*256 + ch*16;
            cp16(d,         g_Rh + ao);
            cp16(d + 8192,  g_Rl + ao);
            cp16(d + 16384, g_Lh + bo);
            cp16(d + 24576, g_Ll + bo);
        }
        CPC();
    };
    issue(0, 0);

    const int m0 = (w&3)*32;         // (j,e) rows: jl = w&3, e = m&31
    const int n0 = (w>>2)*64;        // (i,d) cols: il = (w>>2)*2 + (n>=32)
    const int aLane = lane&15, aK = lane>>4;
    const int bRow = ((lane>>4)<<3) + (lane&7), bK = (lane>>3)&1;
    float C[2][8][4];
    #pragma unroll
    for (int a1 = 0; a1 < 2; a1++)
        #pragma unroll
        for (int a2 = 0; a2 < 8; a2++)
            #pragma unroll
            for (int a3 = 0; a3 < 4; a3++) C[a1][a2][a3] = 0.f;

    #pragma unroll 1
    for (int c = 0; c < 4; c++){
        __syncthreads();
        if (c+1 < 4){ issue(c+1, (c+1)&1); CPW1(); } else CPW0();
        __syncthreads();
        const u32 Ab = sb + (c&1)*32768;
        const u32 Bb = Ab + 16384;
        #pragma unroll
        for (int ks = 0; ks < 2; ks++){
            u32 Ah[2][4], Al[2][4];
            #pragma unroll
            for (int mh = 0; mh < 2; mh++){
                int r = m0 + mh*16 + aLane;
                u32 kc = ks*2 + aK;
                u32 ac = (u32)r*64 + ((kc ^ ((r>>1)&3))<<4);
                LDSM4(Ah[mh], Ab + ac);
                LDSM4(Al[mh], Ab + 8192 + ac);
            }
            #pragma unroll
            for (int bp = 0; bp < 4; bp++){
                u32 Bh[4], Bl[4];
                int r0 = n0 + bp*16 + bRow;
                u32 kc = ks*2 + bK;
                u32 bc = (u32)r0*64 + ((kc ^ ((r0>>1)&3))<<4);
                LDSM4(Bh, Bb + bc);
                LDSM4(Bl, Bb + 8192 + bc);
                #pragma unroll
                for (int mh = 0; mh < 2; mh++){
                    MMA(C[mh][2*bp],   Ah[mh], Bh[0], Bh[1]);
                    MMA(C[mh][2*bp+1], Ah[mh], Bh[2], Bh[3]);
                    MMA(C[mh][2*bp],   Ah[mh], Bl[0], Bl[1]);
                    MMA(C[mh][2*bp+1], Ah[mh], Bl[2], Bl[3]);
                    MMA(C[mh][2*bp],   Al[mh], Bh[0], Bh[1]);
                    MMA(C[mh][2*bp+1], Al[mh], Bh[2], Bh[3]);
                }
            }
        }
    }
    __syncthreads();   // all LDSM reads done; recycle smem as staging
    // stage: hi [0,32K) rows (il*4+jl)*2048B, lo [32K,64K)
    const int cr = lane>>2, cc = (lane&3)*2;
    const int jl = w&3;
    #pragma unroll
    for (int mh = 0; mh < 2; mh++){
        #pragma unroll
        for (int h = 0; h < 2; h++){
            int e = mh*16 + cr + h*8;
            #pragma unroll
            for (int nt = 0; nt < 8; nt++){
                int n = n0 + (nt>>1)*16 + (nt&1)*8 + cc;
                int il = n>>5, d = n&31;
                u32 H, L;
                packHL(C[mh][nt][2*h], C[mh][nt][2*h+1], H, L);
                u32 so = (u32)((il*4 + jl)*2048 + (e*32 + d)*2);
                *(u32*)(sm1 + so) = H;
                *(u32*)(sm1 + 32768 + so) = L;
            }
        }
    }
    __syncthreads();
    // coalesced flush: 16 G rows x 2048B, hi + lo
    #pragma unroll
    for (int q = 0; q < 8; q++){
        int idx = t + 256*q;               // 0..2047 uint4
        int r16 = idx>>7;                  // il*4+jl
        int wi = (idx&127)*16;
        size_t row = ((size_t)(i0 + (r16>>2))*512 + (j0 + (r16&3)))*2048;
        *(uint4*)(g_Gh + row + wi) = *(const uint4*)(sm1 + r16*2048 + wi);
        *(uint4*)(g_Gl + row + wi) = *(const uint4*)(sm1 + 32768 + r16*2048 + wi);
    }
}

// ================= kB2: out = G x Wt, chunk-major fused 3-product, ring-3 =====
// 32 chunks of k=32. Chunk buffer 32KB: Ah|Al|Bh|Bl. Ring-3 = 96KB.
#define KB2_SMEM (98304 + 1024)
__global__ void __launch_bounds__(256,2) kB2(
    const float* __restrict__ bias, const float* __restrict__ mask, float* __restrict__ out)
{
    extern __shared__ __align__(128) uch sm2[];
    const u32 sb = smem_u32(sm2);
    float* normr = (float*)(sm2 + 98304);
    float* mi    = (float*)(sm2 + 98304 + 512);
    const int t = threadIdx.x, w = t>>5, lane = t&31;
    const int jt2 = blockIdx.x, i = blockIdx.y;

    auto issue = [&](int c, int buf){
        size_t abase = ((size_t)i*512 + jt2*128)*2048 + c*64;
        size_t bbase = (size_t)c*64;
        #pragma unroll
        for (int q = 0; q < 2; q++){
            int v = t+256*q, row = v>>2, ch = v&3;
            u32 sw = (u32)(((u32)ch ^ ((row>>1)&3))<<4);
            u32 d = sb + buf*32768 + row*64 + sw;
            size_t ao = abase + (size_t)row*2048 + ch*16;
            size_t bo = bbase + (size_t)row*2048 + ch*16;
            cp16(d,         g_Gh + ao);
            cp16(d + 8192,  g_Gl + ao);
            cp16(d + 16384, g_Wh + bo);
            cp16(d + 24576, g_Wl + bo);
        }
        CPC();
    };
    issue(0, 0);
    issue(1, 1);
    if (t < 128) mi[t] = mask[t*L_DIM + i];
    __syncthreads();
    if (t < 128){
        float a = 0.f;
        #pragma unroll 8
        for (int s = 0; s < 128; s++) a += mi[s]*mask[s*L_DIM + jt2*128 + t];
        normr[t] = 1.0f/(a + 0.001f);
    }

    const int m0 = (w&3)*32;
    const int f0 = (w>>2)*64;
    const int aLane = lane&15, aK = lane>>4;
    const int bRow = ((lane>>4)<<3) + (lane&7), bK = (lane>>3)&1;
    float C[2][8][4];
    #pragma unroll
    for (int a1 = 0; a1 < 2; a1++)
        #pragma unroll
        for (int a2 = 0; a2 < 8; a2++)
            #pragma unroll
            for (int a3 = 0; a3 < 4; a3++) C[a1][a2][a3] = 0.f;

    #pragma unroll 1
    for (int s = 0; s < 32; s++){
        __syncthreads();                         // compute(s-1) done -> buf (s+2)%3 free
        if (s+2 < 32){ issue(s+2, (s+2)%3); CPW2(); }
        else if (s+1 < 32) CPW1(); else CPW0();
        __syncthreads();                         // chunk s visible
        const u32 Ab = sb + (s%3)*32768;
        const u32 Bb = Ab + 16384;
        #pragma unroll
        for (int ks = 0; ks < 2; ks++){
            u32 Ah[2][4], Al[2][4];
            #pragma unroll
            for (int mh = 0; mh < 2; mh++){
                int r = m0 + mh*16 + aLane;
                u32 kc = ks*2 + aK;
                u32 ac = (u32)r*64 + ((kc ^ ((r>>1)&3))<<4);
                LDSM4(Ah[mh], Ab + ac);
                LDSM4(Al[mh], Ab + 8192 + ac);
            }
            #pragma unroll
            for (int bp = 0; bp < 4; bp++){
                u32 Bh[4], Bl[4];
                int r0 = f0 + bp*16 + bRow;
                u32 kc = ks*2 + bK;
                u32 bc = (u32)r0*64 + ((kc ^ ((r0>>1)&3))<<4);
                LDSM4(Bh, Bb + bc);
                LDSM4(Bl, Bb + 8192 + bc);
                #pragma unroll
                for (int mh = 0; mh < 2; mh++){
                    MMA(C[mh][2*bp],   Ah[mh], Bh[0], Bh[1]);
                    MMA(C[mh][2*bp+1], Ah[mh], Bh[2], Bh[3]);
                    MMA(C[mh][2*bp],   Ah[mh], Bl[0], Bl[1]);
                    MMA(C[mh][2*bp+1], Ah[mh], Bl[2], Bl[3]);
                    MMA(C[mh][2*bp],   Al[mh], Bh[0], Bh[1]);
                    MMA(C[mh][2*bp+1], Al[mh], Bh[2], Bh[3]);
                }
            }
        }
    }
    // epilogue
    const int cr = lane>>2, cc = (lane&3)*2;
    #pragma unroll
    for (int mh = 0; mh < 2; mh++){
        #pragma unroll
        for (int h = 0; h < 2; h++){
            int j = m0 + mh*16 + cr + h*8;
            float nr = normr[j];
            float* op = out + ((size_t)i*512 + jt2*128 + j)*OUT_F;
            #pragma unroll
            for (int nt = 0; nt < 8; nt++){
                int f = f0 + (nt>>1)*16 + (nt&1)*8 + cc;
                float2 o;
                o.x = (C[mh][nt][2*h  ] + bias[f  ])*nr;
                o.y = (C[mh][nt][2*h+1] + bias[f+1])*nr;
                *(float2*)(op + f) = o;
            }
        }
    }
}

// ---------------------------------------------------------------------------
extern "C" void kernel_launch(void* const* d_in, const int* in_sizes, int n_in,
                              void* d_out, int out_size)
{
    const float* node_repr = (const float*)d_in[0];
    const float* mask      = (const float*)d_in[1];
    const float* w_proj    = (const float*)d_in[2];
    const float* b_proj    = (const float*)d_in[3];
    const float* out_w     = (const float*)d_in[4];
    const float* out_bias  = (const float*)d_in[5];
    float* out = (float*)d_out;

    const int smemA = KA_SMEM_FLOATS*4;
    cudaFuncSetAttribute(kA,  cudaFuncAttributeMaxDynamicSharedMemorySize, smemA);
    cudaFuncSetAttribute(kB1, cudaFuncAttributeMaxDynamicSharedMemorySize, KB1_SMEM);
    cudaFuncSetAttribute(kB2, cudaFuncAttributeMaxDynamicSharedMemorySize, KB2_SMEM);

    kA<<<(S_DIM*L_DIM)/32, 256, smemA>>>(node_repr, mask, w_proj, b_proj);
    kW<<<128, 256>>>(out_w);
    kB1<<<dim3(128, 128), 256, KB1_SMEM>>>();
    kB2<<<dim3(4, 512), 256, KB2_SMEM>>>(out_bias, mask, out);
}